// round 8
// baseline (speedup 1.0000x reference)
#include <cuda_runtime.h>
#include <math.h>
#include <stdint.h>

#define N_ENTC 30000
#define N_CONC 29309
#define DIMC   128
#define NBC    8
#define RC     12
#define BBC    256
#define LCC    50
#define SSC    32
#define E_DBC  300000
#define E_CONC 200000
#define NBLKN  235
#define PML    240

// ---------------- scratch ----------------------------------------------------
__device__ __align__(16) float g_w[(size_t)RC * N_ENTC * DIMC];   // 184MB: comp@basis
__device__ __align__(16) float g_db_agg[N_ENTC * DIMC];
__device__ __align__(16) float g_db_cnt[N_ENTC];
__device__ __align__(16) float g_db_feats[N_ENTC * DIMC];
__device__ __align__(16) float g_xw[N_CONC * DIMC];
__device__ __align__(16) float g_con_acc[N_CONC * DIMC];
__device__ __align__(16) float g_con_feats[N_CONC * DIMC];
__device__ __align__(16) float g_deg[29312];
__device__ __align__(16) float g_dinv[29312];
__device__ __align__(16) float g_e_db[BBC * SSC];
__device__ __align__(16) float g_e_con[BBC * LCC];
__device__ __align__(16) float g_db_user[BBC * DIMC];
__device__ __align__(16) float g_con_user[BBC * DIMC];
__device__ __align__(16) float g_mask[BBC];
__device__ __align__(16) float g_user_emb[BBC * DIMC];
__device__ __align__(16) float g_con_e[BBC * DIMC];
__device__ __align__(16) float g_info_partial[BBC];
__device__ __align__(16) float g_bmax[BBC];
__device__ __align__(16) float g_bZ[BBC];
__device__ __align__(16) float g_pm[BBC * PML];
__device__ __align__(16) float g_pz[BBC * PML];

#define FMA2(c, a, b) asm("fma.rn.f32x2 %0, %1, %2, %0;" : "+l"(c) : "l"(a), "l"(b))
#define PACK2(d, f)   asm("mov.b64 %0, {%1, %1};" : "=l"(d) : "f"(f))

// ---------------- zero scratch ------------------------------------------------
__global__ void k_zero() {
    int i = blockIdx.x * blockDim.x + threadIdx.x;
    float4 z = make_float4(0.f, 0.f, 0.f, 0.f);
    if (i < N_ENTC * DIMC / 4) reinterpret_cast<float4*>(g_db_agg)[i] = z;
    if (i < N_CONC * DIMC / 4) reinterpret_cast<float4*>(g_con_acc)[i] = z;
    if (i < N_ENTC / 4)        reinterpret_cast<float4*>(g_db_cnt)[i] = z;
    if (i < 29312 / 4)         reinterpret_cast<float4*>(g_deg)[i] = z;
    if (i < BBC / 4)           reinterpret_cast<float4*>(g_info_partial)[i] = z;
}

// ---------------- W = einsum('rb,bnd->rnd', comp, basis) ----------------------
__global__ __launch_bounds__(256) void k_wbuild(
    const float* __restrict__ comp, const float* __restrict__ basis)
{
    __shared__ float sc[RC][NBC];
    int tid = threadIdx.x;
    if (tid < RC * NBC) ((float*)sc)[tid] = comp[tid];
    __syncthreads();
    int i = blockIdx.x * 256 + tid;
    if (i >= N_ENTC * 32) return;
    int n = i >> 5, q = i & 31;
    float4 bas[NBC];
#pragma unroll
    for (int b = 0; b < NBC; b++)
        bas[b] = __ldg(reinterpret_cast<const float4*>(
            &basis[((size_t)b * N_ENTC + n) * DIMC + q * 4]));
#pragma unroll
    for (int r = 0; r < RC; r++) {
        float4 o = make_float4(0.f, 0.f, 0.f, 0.f);
#pragma unroll
        for (int b = 0; b < NBC; b++) {
            float c = sc[r][b];
            o.x = fmaf(c, bas[b].x, o.x); o.y = fmaf(c, bas[b].y, o.y);
            o.z = fmaf(c, bas[b].z, o.z); o.w = fmaf(c, bas[b].w, o.w);
        }
        *reinterpret_cast<float4*>(&g_w[((size_t)r * N_ENTC + n) * DIMC + q * 4]) = o;
    }
}

// ---------------- RGCN scatter: one W row per edge -----------------------------
__global__ __launch_bounds__(256) void k_rgcn_scatter(
    const int* __restrict__ ei, const int* __restrict__ et)
{
    int w = (blockIdx.x * blockDim.x + threadIdx.x) >> 5;
    int lane = threadIdx.x & 31;
    if (w >= E_DBC) return;
    int src = ei[w];
    int dst = ei[E_DBC + w];
    int r   = et[w];
    float4 v = __ldg(reinterpret_cast<const float4*>(
        &g_w[((size_t)r * N_ENTC + src) * DIMC + lane * 4]));
    float* dsta = &g_db_agg[(size_t)dst * DIMC + lane * 4];
    asm volatile("red.global.add.v4.f32 [%0], {%1, %2, %3, %4};"
                 :: "l"(dsta), "f"(v.x), "f"(v.y), "f"(v.z), "f"(v.w)
                 : "memory");
    if (lane == 0) atomicAdd(&g_db_cnt[dst], 1.f);
}

__global__ void k_rgcn_fin(const float* __restrict__ root, const float* __restrict__ bias) {
    int i = blockIdx.x * blockDim.x + threadIdx.x;
    if (i >= N_ENTC * DIMC / 4) return;
    int n = i >> 5, dq = i & 31;
    float inv = 1.f / fmaxf(g_db_cnt[n], 1.f);
    float4 a = reinterpret_cast<const float4*>(g_db_agg)[i];
    float4 r = reinterpret_cast<const float4*>(root)[i];
    float4 bs = reinterpret_cast<const float4*>(bias)[dq];
    float4 o;
    o.x = a.x * inv + r.x + bs.x; o.y = a.y * inv + r.y + bs.y;
    o.z = a.z * inv + r.z + bs.z; o.w = a.w * inv + r.w + bs.w;
    reinterpret_cast<float4*>(g_db_feats)[i] = o;
}

// ---------------- GCN over concepts -------------------------------------------
__global__ void k_deg(const int* __restrict__ cei) {
    int e = blockIdx.x * blockDim.x + threadIdx.x;
    if (e < E_CONC) atomicAdd(&g_deg[cei[E_CONC + e]], 1.f);
}

__global__ void k_dinv() {
    int i = blockIdx.x * blockDim.x + threadIdx.x;
    if (i < N_CONC) g_dinv[i] = rsqrtf(g_deg[i] + 1.0f);
}

#define XR2 32
__global__ __launch_bounds__(128) void k_xw(const float* __restrict__ emb,
                                            const float* __restrict__ W) {
    int g0 = blockIdx.x * XR2;
    int d = threadIdx.x;
    __shared__ __align__(16) float sh[DIMC][XR2];
    int nr = N_CONC - g0; if (nr > XR2) nr = XR2;
#pragma unroll 4
    for (int r = 0; r < XR2; r++)
        sh[d][r] = (r < nr) ? emb[(size_t)(g0 + r) * DIMC + d] : 0.f;
    __syncthreads();
    unsigned long long acc[XR2 / 2];
#pragma unroll
    for (int q = 0; q < XR2 / 2; q++) acc[q] = 0ULL;
#pragma unroll 4
    for (int k = 0; k < DIMC; k++) {
        float w = W[k * DIMC + d];
        unsigned long long wp;
        PACK2(wp, w);
        const ulonglong2* ep = reinterpret_cast<const ulonglong2*>(&sh[k][0]);
#pragma unroll
        for (int q = 0; q < XR2 / 4; q++) {
            ulonglong2 e2 = ep[q];
            FMA2(acc[2 * q],     e2.x, wp);
            FMA2(acc[2 * q + 1], e2.y, wp);
        }
    }
    for (int r = 0; r < nr; r++) {
        unsigned long long v = acc[r >> 1];
        float f = (r & 1) ? __uint_as_float((unsigned)(v >> 32))
                          : __uint_as_float((unsigned)v);
        g_xw[(size_t)(g0 + r) * DIMC + d] = f;
    }
}

__global__ __launch_bounds__(256) void k_gcn_scatter(const int* __restrict__ cei) {
    int w = (blockIdx.x * blockDim.x + threadIdx.x) >> 5;
    int lane = threadIdx.x & 31;
    if (w >= E_CONC) return;
    int s = cei[w];
    int t = cei[E_CONC + w];
    float nm = g_dinv[s] * g_dinv[t];
    const float4* xp = reinterpret_cast<const float4*>(&g_xw[(size_t)s * DIMC]);
    float4 v = __ldg(&xp[lane]);
    float* dsta = &g_con_acc[(size_t)t * DIMC + lane * 4];
    asm volatile("red.global.add.v4.f32 [%0], {%1, %2, %3, %4};"
                 :: "l"(dsta), "f"(nm * v.x), "f"(nm * v.y), "f"(nm * v.z), "f"(nm * v.w)
                 : "memory");
}

__global__ void k_gcn_fin(const float* __restrict__ gb) {
    int i = blockIdx.x * blockDim.x + threadIdx.x;
    if (i >= N_CONC * DIMC / 4) return;
    int n = i >> 5, dq = i & 31;
    float di = g_dinv[n];
    float sl = di * di;
    float4 a = reinterpret_cast<const float4*>(g_con_acc)[i];
    float4 x = reinterpret_cast<const float4*>(g_xw)[i];
    float4 bs = reinterpret_cast<const float4*>(gb)[dq];
    float4 o;
    o.x = a.x + sl * x.x + bs.x; o.y = a.y + sl * x.y + bs.y;
    o.z = a.z + sl * x.z + bs.z; o.w = a.w + sl * x.w + bs.w;
    reinterpret_cast<float4*>(g_con_feats)[i] = o;
}

// ---------------- attention e-scores as tiled GEMM -----------------------------
#define EM  64
#define EKC 32
#define EHP 68
#define EAP 132
__global__ __launch_bounds__(256, 2) void k_attn_e(
    const float* __restrict__ feats, const int* __restrict__ idxarr,
    const float* __restrict__ A, const float* __restrict__ bv,
    float* __restrict__ eout)
{
    __shared__ __align__(16) float sH[EKC * EHP];
    __shared__ __align__(16) float sA[EKC * EAP];
    int tid = threadIdx.x;
    int tx = tid & 15, ty = tid >> 4;
    int m0 = ty * 4, n0 = tx * 8;
    int bm = blockIdx.x * EM;
    unsigned long long c[4][4];
#pragma unroll
    for (int i = 0; i < 4; i++)
#pragma unroll
        for (int j = 0; j < 4; j++) c[i][j] = 0ULL;

    for (int kc = 0; kc < DIMC; kc += EKC) {
#pragma unroll
        for (int it = 0; it < 2; it++) {
            int idx = tid + it * 256;
            int row = idx >> 3;
            int kq = idx & 7;
            int gi = idxarr[bm + row];
            float4 h = *reinterpret_cast<const float4*>(
                &feats[(size_t)gi * DIMC + kc + kq * 4]);
            int kk = kq * 4;
            sH[(kk + 0) * EHP + row] = h.x; sH[(kk + 1) * EHP + row] = h.y;
            sH[(kk + 2) * EHP + row] = h.z; sH[(kk + 3) * EHP + row] = h.w;
        }
#pragma unroll
        for (int it = 0; it < 4; it++) {
            int idx = tid + it * 256;
            int ar = idx >> 5;
            int ac = idx & 31;
            float4 a = *reinterpret_cast<const float4*>(
                &A[(size_t)(kc + ar) * DIMC + ac * 4]);
            *reinterpret_cast<float4*>(&sA[ar * EAP + ac * 4]) = a;
        }
        __syncthreads();
#pragma unroll 4
        for (int kk = 0; kk < EKC; kk++) {
            float4 h4 = *reinterpret_cast<const float4*>(&sH[kk * EHP + m0]);
            ulonglong2 q0 = *reinterpret_cast<const ulonglong2*>(&sA[kk * EAP + n0]);
            ulonglong2 q1 = *reinterpret_cast<const ulonglong2*>(&sA[kk * EAP + n0 + 4]);
            float hv[4] = {h4.x, h4.y, h4.z, h4.w};
#pragma unroll
            for (int i = 0; i < 4; i++) {
                unsigned long long p;
                PACK2(p, hv[i]);
                FMA2(c[i][0], p, q0.x); FMA2(c[i][1], p, q0.y);
                FMA2(c[i][2], p, q1.x); FMA2(c[i][3], p, q1.y);
            }
        }
        __syncthreads();
    }
    float4 bva = *reinterpret_cast<const float4*>(&bv[n0]);
    float4 bvb = *reinterpret_cast<const float4*>(&bv[n0 + 4]);
    float bb[8] = {bva.x, bva.y, bva.z, bva.w, bvb.x, bvb.y, bvb.z, bvb.w};
#pragma unroll
    for (int i = 0; i < 4; i++) {
        float ep = 0.f;
#pragma unroll
        for (int j = 0; j < 4; j++) {
            float lo = __uint_as_float((unsigned)c[i][j]);
            float hi = __uint_as_float((unsigned)(c[i][j] >> 32));
            ep += tanhf(lo) * bb[2 * j] + tanhf(hi) * bb[2 * j + 1];
        }
#pragma unroll
        for (int o = 8; o; o >>= 1) ep += __shfl_xor_sync(0xffffffffu, ep, o);
        if (tx == 0) eout[bm + m0 + i] = ep;
    }
}

// ---------------- attention finish: softmax + weighted sum ---------------------
__global__ __launch_bounds__(128) void k_attn_fin_db(
    const int* __restrict__ seed_pad, const int* __restrict__ seed_lens)
{
    int b = blockIdx.x, d = threadIdx.x;
    __shared__ float e_sh[SSC], a_sh[SSC];
    __shared__ int idx_sh[SSC];
    int len = seed_lens[b];
    if (d < SSC) {
        e_sh[d] = g_e_db[b * SSC + d];
        idx_sh[d] = seed_pad[b * SSC + d];
    }
    __syncthreads();
    if (d == 0) {
        float m = -3.0e38f;
        float v[SSC];
        for (int s = 0; s < SSC; s++) {
            v[s] = (s < len) ? e_sh[s] : -1e30f;
            m = fmaxf(m, v[s]);
        }
        float Z = 0.f;
        for (int s = 0; s < SSC; s++) { float w = expf(v[s] - m); a_sh[s] = w; Z += w; }
        float inv = 1.f / Z;
        for (int s = 0; s < SSC; s++) a_sh[s] *= inv;
    }
    __syncthreads();
    float du = 0.f;
#pragma unroll 8
    for (int s = 0; s < SSC; s++)
        du += a_sh[s] * g_db_feats[(size_t)idx_sh[s] * DIMC + d];
    if (len <= 0) du = 0.f;
    g_db_user[b * DIMC + d] = du;
    if (d == 0) g_mask[b] = (len > 0) ? 1.f : 0.f;
}

__global__ __launch_bounds__(128) void k_attn_fin_con(const int* __restrict__ cm) {
    int b = blockIdx.x, d = threadIdx.x;
    __shared__ float e_sh[LCC], a_sh[LCC];
    __shared__ int idx_sh[LCC];
    if (d < LCC) {
        e_sh[d] = g_e_con[b * LCC + d];
        idx_sh[d] = cm[b * LCC + d];
    }
    __syncthreads();
    if (d == 0) {
        float m = -3.0e38f;
        float v[LCC];
        for (int s = 0; s < LCC; s++) {
            v[s] = (idx_sh[s] != 0) ? e_sh[s] : -1e30f;
            m = fmaxf(m, v[s]);
        }
        float Z = 0.f;
        for (int s = 0; s < LCC; s++) { float w = expf(v[s] - m); a_sh[s] = w; Z += w; }
        float inv = 1.f / Z;
        for (int s = 0; s < LCC; s++) a_sh[s] *= inv;
    }
    __syncthreads();
    float cu = 0.f;
#pragma unroll 10
    for (int s = 0; s < LCC; s++)
        cu += a_sh[s] * g_con_feats[(size_t)idx_sh[s] * DIMC + d];
    g_con_user[b * DIMC + d] = cu;
}

// ---------------- gated fusion + info projection -------------------------------
__global__ __launch_bounds__(128) void k_fuse(
    const float* __restrict__ unw, const float* __restrict__ unb,
    const float* __restrict__ gw, const float* __restrict__ gb,
    const float* __restrict__ icw, const float* __restrict__ icb)
{
    int b = blockIdx.x, d = threadIdx.x;
    __shared__ __align__(16) float cat[2 * DIMC];
    __shared__ float redv[4];
    __shared__ float sg;
    cat[d] = g_con_user[b * DIMC + d];
    cat[DIMC + d] = g_db_user[b * DIMC + d];
    __syncthreads();
    float u = unb[d];
    {
        const float4* wr = reinterpret_cast<const float4*>(unw + (size_t)d * 2 * DIMC);
        const float4* cp = reinterpret_cast<const float4*>(cat);
#pragma unroll 8
        for (int q = 0; q < (2 * DIMC) / 4; q++) {
            float4 w4 = wr[q]; float4 c4 = cp[q];
            u += w4.x * c4.x + w4.y * c4.y + w4.z * c4.z + w4.w * c4.w;
        }
    }
    float gv = u * gw[d];
    int lane = d & 31, wd = d >> 5;
#pragma unroll
    for (int o = 16; o; o >>= 1) gv += __shfl_down_sync(0xffffffffu, gv, o);
    if (lane == 0) redv[wd] = gv;
    __syncthreads();
    if (d == 0) {
        float s = redv[0] + redv[1] + redv[2] + redv[3] + gb[0];
        sg = 1.f / (1.f + expf(-s));
    }
    __syncthreads();
    float g = sg;
    float cu = cat[d], du = cat[DIMC + d];
    g_user_emb[b * DIMC + d] = g * du + (1.f - g) * cu;
    float ce = icb[d];
    {
        const float4* ir = reinterpret_cast<const float4*>(icw + (size_t)d * DIMC);
        const float4* cp = reinterpret_cast<const float4*>(cat);
#pragma unroll 8
        for (int q = 0; q < DIMC / 4; q++) {
            float4 w4 = ir[q]; float4 c4 = cp[q];
            ce += w4.x * c4.x + w4.y * c4.y + w4.z * c4.z + w4.w * c4.w;
        }
    }
    g_con_e[b * DIMC + d] = ce;
}

// ---------------- fused dual GEMM + softmax partials + MSE --------------------
#define GBM 64
#define GBN 128
#define GKC 32
#define SAP 68
#define SBP 132
__global__ __launch_bounds__(128, 2) void k_score_gemm(
    const float* __restrict__ enb, const float* __restrict__ infb,
    const float* __restrict__ dbvec, float* __restrict__ out, int off)
{
    __shared__ __align__(16) float sA1[GKC * SAP];
    __shared__ __align__(16) float sA2[GKC * SAP];
    __shared__ __align__(16) float sB[GKC * SBP];
    int tid = threadIdx.x;
    int tx = tid & 15, ty = tid >> 4;
    int m0 = ty * 8, n0 = tx * 8;
    int bn = blockIdx.x * GBN, bm = blockIdx.y * GBM;
    unsigned long long c1[8][4], c2[8][4];
#pragma unroll
    for (int i = 0; i < 8; i++)
#pragma unroll
        for (int j = 0; j < 4; j++) { c1[i][j] = 0ULL; c2[i][j] = 0ULL; }

    for (int kc = 0; kc < DIMC; kc += GKC) {
#pragma unroll
        for (int it = 0; it < 4; it++) {
            int idx = tid + it * 128;
            int row = idx >> 3;
            int kq = idx & 7;
            float4 a1 = *reinterpret_cast<const float4*>(
                &g_user_emb[(size_t)(bm + row) * DIMC + kc + kq * 4]);
            float4 a2 = *reinterpret_cast<const float4*>(
                &g_con_e[(size_t)(bm + row) * DIMC + kc + kq * 4]);
            int kk = kq * 4;
            sA1[(kk + 0) * SAP + row] = a1.x; sA1[(kk + 1) * SAP + row] = a1.y;
            sA1[(kk + 2) * SAP + row] = a1.z; sA1[(kk + 3) * SAP + row] = a1.w;
            sA2[(kk + 0) * SAP + row] = a2.x; sA2[(kk + 1) * SAP + row] = a2.y;
            sA2[(kk + 2) * SAP + row] = a2.z; sA2[(kk + 3) * SAP + row] = a2.w;
        }
#pragma unroll
        for (int it = 0; it < 8; it++) {
            int idx = tid + it * 128;
            int row = idx >> 3;
            int kq = idx & 7;
            int gn = bn + row;
            float4 bb = make_float4(0.f, 0.f, 0.f, 0.f);
            if (gn < N_ENTC)
                bb = *reinterpret_cast<const float4*>(
                    &g_db_feats[(size_t)gn * DIMC + kc + kq * 4]);
            int kk = kq * 4;
            sB[(kk + 0) * SBP + row] = bb.x; sB[(kk + 1) * SBP + row] = bb.y;
            sB[(kk + 2) * SBP + row] = bb.z; sB[(kk + 3) * SBP + row] = bb.w;
        }
        __syncthreads();
#pragma unroll 4
        for (int kk = 0; kk < GKC; kk++) {
            float4 a1lo = *reinterpret_cast<const float4*>(&sA1[kk * SAP + m0]);
            float4 a1hi = *reinterpret_cast<const float4*>(&sA1[kk * SAP + m0 + 4]);
            float4 a2lo = *reinterpret_cast<const float4*>(&sA2[kk * SAP + m0]);
            float4 a2hi = *reinterpret_cast<const float4*>(&sA2[kk * SAP + m0 + 4]);
            ulonglong2 q0 = *reinterpret_cast<const ulonglong2*>(&sB[kk * SBP + n0]);
            ulonglong2 q1 = *reinterpret_cast<const ulonglong2*>(&sB[kk * SBP + n0 + 4]);
            unsigned long long b0 = q0.x, b1 = q0.y, b2 = q1.x, b3 = q1.y;
            float av1[8] = {a1lo.x, a1lo.y, a1lo.z, a1lo.w, a1hi.x, a1hi.y, a1hi.z, a1hi.w};
            float av2[8] = {a2lo.x, a2lo.y, a2lo.z, a2lo.w, a2hi.x, a2hi.y, a2hi.z, a2hi.w};
#pragma unroll
            for (int i = 0; i < 8; i++) {
                unsigned long long p1, p2;
                PACK2(p1, av1[i]);
                PACK2(p2, av2[i]);
                FMA2(c1[i][0], p1, b0); FMA2(c1[i][1], p1, b1);
                FMA2(c1[i][2], p1, b2); FMA2(c1[i][3], p1, b3);
                FMA2(c2[i][0], p2, b0); FMA2(c2[i][1], p2, b1);
                FMA2(c2[i][2], p2, b2); FMA2(c2[i][3], p2, b3);
            }
        }
        __syncthreads();
    }

    bool tail = (bn + GBN > N_ENTC);
    float* orow_base = out + off;
#pragma unroll
    for (int i = 0; i < 8; i++) {
        int gm = bm + m0 + i;
        float es[8], dd[8];
#pragma unroll
        for (int j = 0; j < 4; j++) {
            es[2 * j]     = __uint_as_float((unsigned)c1[i][j]);
            es[2 * j + 1] = __uint_as_float((unsigned)(c1[i][j] >> 32));
            dd[2 * j]     = __uint_as_float((unsigned)c2[i][j]);
            dd[2 * j + 1] = __uint_as_float((unsigned)(c2[i][j] >> 32));
        }
        float mx = -3.0e38f, sq = 0.f;
        float* orow = orow_base + (size_t)gm * N_ENTC + bn + n0;
        if (!tail) {
            float4 e4a = *reinterpret_cast<const float4*>(&enb[bn + n0]);
            float4 e4b = *reinterpret_cast<const float4*>(&enb[bn + n0 + 4]);
            float4 i4a = *reinterpret_cast<const float4*>(&infb[bn + n0]);
            float4 i4b = *reinterpret_cast<const float4*>(&infb[bn + n0 + 4]);
            float4 v4a = *reinterpret_cast<const float4*>(&dbvec[(size_t)gm * N_ENTC + bn + n0]);
            float4 v4b = *reinterpret_cast<const float4*>(&dbvec[(size_t)gm * N_ENTC + bn + n0 + 4]);
            float eb[8] = {e4a.x, e4a.y, e4a.z, e4a.w, e4b.x, e4b.y, e4b.z, e4b.w};
            float ib[8] = {i4a.x, i4a.y, i4a.z, i4a.w, i4b.x, i4b.y, i4b.z, i4b.w};
            float vv[8] = {v4a.x, v4a.y, v4a.z, v4a.w, v4b.x, v4b.y, v4b.z, v4b.w};
#pragma unroll
            for (int j = 0; j < 8; j++) {
                es[j] += eb[j];
                mx = fmaxf(mx, es[j]);
                float df = dd[j] + ib[j] - vv[j];
                sq += df * df;
                orow[j] = es[j];
            }
        } else {
#pragma unroll
            for (int j = 0; j < 8; j++) {
                int gn = bn + n0 + j;
                if (gn < N_ENTC) {
                    es[j] += enb[gn];
                    mx = fmaxf(mx, es[j]);
                    float df = dd[j] + infb[gn] - dbvec[(size_t)gm * N_ENTC + gn];
                    sq += df * df;
                    orow[j] = es[j];
                } else {
                    es[j] = -3.0e38f;
                }
            }
        }
#pragma unroll
        for (int o = 8; o; o >>= 1) mx = fmaxf(mx, __shfl_xor_sync(0xffffffffu, mx, o));
        float z = 0.f;
#pragma unroll
        for (int j = 0; j < 8; j++) z += __expf(es[j] - mx);
#pragma unroll
        for (int o = 8; o; o >>= 1) {
            z  += __shfl_xor_sync(0xffffffffu, z, o);
            sq += __shfl_xor_sync(0xffffffffu, sq, o);
        }
        if (tx == 0) {
            g_pm[gm * PML + blockIdx.x] = mx;
            g_pz[gm * PML + blockIdx.x] = z;
            atomicAdd(&g_info_partial[gm], sq);
        }
    }
}

// ---------------- softmax partial reduce ---------------------------------------
__global__ __launch_bounds__(256) void k_stats_reduce() {
    int b = blockIdx.x, t = threadIdx.x;
    __shared__ float sm[256], sz[256];
    float m = (t < NBLKN) ? g_pm[b * PML + t] : -3.0e38f;
    sm[t] = m;
    __syncthreads();
    for (int o = 128; o; o >>= 1) {
        if (t < o) sm[t] = fmaxf(sm[t], sm[t + o]);
        __syncthreads();
    }
    float M = sm[0];
    float z = (t < NBLKN) ? g_pz[b * PML + t] * __expf(m - M) : 0.f;
    sz[t] = z;
    __syncthreads();
    for (int o = 128; o; o >>= 1) {
        if (t < o) sz[t] += sz[t + o];
        __syncthreads();
    }
    if (t == 0) { g_bmax[b] = M; g_bZ[b] = sz[0]; }
}

// ---------------- final loss ----------------------------------------------------
__global__ __launch_bounds__(256) void k_final(
    const int* __restrict__ labels, const float* __restrict__ rec,
    float* __restrict__ out, int off)
{
    int b = threadIdx.x;
    int lab = labels[b];
    if (lab < 0) lab = 0;
    if (lab >= N_ENTC) lab = N_ENTC - 1;
    float es = out[off + (size_t)b * N_ENTC + lab];
    float ce = (g_bmax[b] + logf(g_bZ[b])) - es;
    float rv = ce * rec[b];
    float iv = g_info_partial[b] * g_mask[b];
    __shared__ float s1[256], s2[256];
    s1[b] = rv; s2[b] = iv;
    __syncthreads();
    for (int o = 128; o; o >>= 1) {
        if (b < o) { s1[b] += s1[b + o]; s2[b] += s2[b + o]; }
        __syncthreads();
    }
    if (b == 0) {
        float rl = s1[0];
        float loss = rl + 0.025f * (s2[0] / (float)BBC);
        if (off) {
            out[0] = loss;
            out[1 + (size_t)BBC * N_ENTC] = rl;
        }
    }
}

// ---------------- launch ---------------------------------------------------------
extern "C" void kernel_launch(void* const* d_in, const int* in_sizes, int n_in,
                              void* d_out, int out_size) {
    const int*   concept_mask = (const int*)d_in[0];
    const int*   seed_pad     = (const int*)d_in[1];
    const int*   seed_lens    = (const int*)d_in[2];
    const int*   db_ei        = (const int*)d_in[3];
    const int*   db_et        = (const int*)d_in[4];
    const int*   con_ei       = (const int*)d_in[5];
    const float* db_vec       = (const float*)d_in[6];
    const int*   labels       = (const int*)d_in[7];
    const float* rec          = (const float*)d_in[8];
    const float* concept_emb  = (const float*)d_in[9];
    const float* basis        = (const float*)d_in[10];
    const float* comp         = (const float*)d_in[11];
    const float* rgcn_root    = (const float*)d_in[12];
    const float* rgcn_bias    = (const float*)d_in[13];
    const float* gcn_w        = (const float*)d_in[14];
    const float* gcn_b        = (const float*)d_in[15];
    const float* attn_a       = (const float*)d_in[16];
    const float* attn_b       = (const float*)d_in[17];
    const float* attn_a_db    = (const float*)d_in[18];
    const float* attn_b_db    = (const float*)d_in[19];
    const float* user_norm_w  = (const float*)d_in[20];
    const float* user_norm_b  = (const float*)d_in[21];
    const float* gate_norm_w  = (const float*)d_in[22];
    const float* gate_norm_b  = (const float*)d_in[23];
    const float* info_con_w   = (const float*)d_in[24];
    const float* info_con_b   = (const float*)d_in[25];
    const float* info_out_db_b= (const float*)d_in[26];
    const float* output_en_b  = (const float*)d_in[27];
    float* out = (float*)d_out;

    long long total = (long long)BBC * N_ENTC;
    int off = ((long long)out_size >= total + 2) ? 1 : 0;

    static cudaStream_t s1 = nullptr, s2 = nullptr;
    static cudaEvent_t eF = nullptr, eZ = nullptr, eJ1 = nullptr, eJ2 = nullptr;
    if (s1 == nullptr) {
        cudaStreamCreateWithFlags(&s1, cudaStreamNonBlocking);
        cudaStreamCreateWithFlags(&s2, cudaStreamNonBlocking);
        cudaEventCreateWithFlags(&eF, cudaEventDisableTiming);
        cudaEventCreateWithFlags(&eZ, cudaEventDisableTiming);
        cudaEventCreateWithFlags(&eJ1, cudaEventDisableTiming);
        cudaEventCreateWithFlags(&eJ2, cudaEventDisableTiming);
    }

    // fork s1 immediately: wbuild is independent of the zero pass
    cudaEventRecord(eF, 0);
    cudaStreamWaitEvent(s1, eF, 0);
    k_wbuild<<<(N_ENTC * 32 + 255) / 256, 256, 0, s1>>>(comp, basis);

    // zero runs concurrently on default stream
    k_zero<<<3750, 256>>>();
    cudaEventRecord(eZ, 0);
    cudaStreamWaitEvent(s1, eZ, 0);   // scatter needs zeroed agg/cnt
    cudaStreamWaitEvent(s2, eZ, 0);   // deg/gcn need zeroed deg/con_acc

    // chain 1: RGCN/db path
    k_rgcn_scatter<<<(E_DBC * 32 + 255) / 256, 256, 0, s1>>>(db_ei, db_et);
    k_rgcn_fin<<<(N_ENTC * DIMC / 4 + 255) / 256, 256, 0, s1>>>(rgcn_root, rgcn_bias);
    k_attn_e<<<BBC * SSC / EM, 256, 0, s1>>>(g_db_feats, seed_pad, attn_a_db, attn_b_db, g_e_db);
    k_attn_fin_db<<<BBC, 128, 0, s1>>>(seed_pad, seed_lens);

    // chain 2: GCN/concept path
    k_deg<<<(E_CONC + 255) / 256, 256, 0, s2>>>(con_ei);
    k_dinv<<<(N_CONC + 255) / 256, 256, 0, s2>>>();
    k_xw<<<(N_CONC + XR2 - 1) / XR2, 128, 0, s2>>>(concept_emb, gcn_w);
    k_gcn_scatter<<<(E_CONC * 32 + 255) / 256, 256, 0, s2>>>(con_ei);
    k_gcn_fin<<<(N_CONC * DIMC / 4 + 255) / 256, 256, 0, s2>>>(gcn_b);
    k_attn_e<<<BBC * LCC / EM, 256, 0, s2>>>(g_con_feats, concept_mask, attn_a, attn_b, g_e_con);
    k_attn_fin_con<<<BBC, 128, 0, s2>>>(concept_mask);

    cudaEventRecord(eJ1, s1);
    cudaEventRecord(eJ2, s2);
    cudaStreamWaitEvent(0, eJ1, 0);
    cudaStreamWaitEvent(0, eJ2, 0);

    k_fuse<<<BBC, 128>>>(user_norm_w, user_norm_b, gate_norm_w, gate_norm_b,
                         info_con_w, info_con_b);
    dim3 gg(NBLKN, BBC / GBM);
    k_score_gemm<<<gg, 128>>>(output_en_b, info_out_db_b, db_vec, out, off);
    k_stats_reduce<<<BBC, 256>>>();
    k_final<<<1, 256>>>(labels, rec, out, off);
}

// round 9
// speedup vs baseline: 1.0925x; 1.0925x over previous
#include <cuda_runtime.h>
#include <math.h>
#include <stdint.h>

#define N_ENTC 30000
#define N_CONC 29309
#define DIMC   128
#define NBC    8
#define RC     12
#define BBC    256
#define LCC    50
#define SSC    32
#define E_DBC  300000
#define E_CONC 200000
#define NBLKN  235
#define PML    240

// ---------------- scratch ----------------------------------------------------
__device__ __align__(16) float g_w[(size_t)RC * N_ENTC * DIMC];   // 184MB: comp@basis
__device__ __align__(16) float g_db_agg[N_ENTC * DIMC];
__device__ __align__(16) float g_db_cnt[N_ENTC];
__device__ __align__(16) float g_db_feats[N_ENTC * DIMC];
__device__ __align__(16) float g_xw[N_CONC * DIMC];
__device__ __align__(16) float g_con_acc[N_CONC * DIMC];
__device__ __align__(16) float g_con_feats[N_CONC * DIMC];
__device__ __align__(16) float g_deg[29312];
__device__ __align__(16) float g_dinv[29312];
__device__ __align__(16) float g_e_db[BBC * SSC];
__device__ __align__(16) float g_e_con[BBC * LCC];
__device__ __align__(16) float g_db_user[BBC * DIMC];
__device__ __align__(16) float g_con_user[BBC * DIMC];
__device__ __align__(16) float g_mask[BBC];
__device__ __align__(16) float g_user_emb[BBC * DIMC];
__device__ __align__(16) float g_con_e[BBC * DIMC];
__device__ __align__(16) float g_info_partial[BBC];
__device__ __align__(16) float g_bmax[BBC];
__device__ __align__(16) float g_bZ[BBC];
__device__ __align__(16) float g_pm[BBC * PML];
__device__ __align__(16) float g_pz[BBC * PML];

#define FMA2(c, a, b) asm("fma.rn.f32x2 %0, %1, %2, %0;" : "+l"(c) : "l"(a), "l"(b))
#define PACK2(d, f)   asm("mov.b64 %0, {%1, %1};" : "=l"(d) : "f"(f))

// ---------------- zero scratch ------------------------------------------------
__global__ void k_zero() {
    int i = blockIdx.x * blockDim.x + threadIdx.x;
    float4 z = make_float4(0.f, 0.f, 0.f, 0.f);
    if (i < N_ENTC * DIMC / 4) reinterpret_cast<float4*>(g_db_agg)[i] = z;
    if (i < N_CONC * DIMC / 4) reinterpret_cast<float4*>(g_con_acc)[i] = z;
    if (i < N_ENTC / 4)        reinterpret_cast<float4*>(g_db_cnt)[i] = z;
    if (i < 29312 / 4)         reinterpret_cast<float4*>(g_deg)[i] = z;
    if (i < BBC / 4)           reinterpret_cast<float4*>(g_info_partial)[i] = z;
}

// ---------------- W = einsum('rb,bnd->rnd', comp, basis) ----------------------
__global__ __launch_bounds__(256) void k_wbuild(
    const float* __restrict__ comp, const float* __restrict__ basis)
{
    __shared__ float sc[RC][NBC];
    int tid = threadIdx.x;
    if (tid < RC * NBC) ((float*)sc)[tid] = comp[tid];
    __syncthreads();
    int i = blockIdx.x * 256 + tid;
    if (i >= N_ENTC * 32) return;
    int n = i >> 5, q = i & 31;
    float4 bas[NBC];
#pragma unroll
    for (int b = 0; b < NBC; b++)
        bas[b] = __ldg(reinterpret_cast<const float4*>(
            &basis[((size_t)b * N_ENTC + n) * DIMC + q * 4]));
#pragma unroll
    for (int r = 0; r < RC; r++) {
        float4 o = make_float4(0.f, 0.f, 0.f, 0.f);
#pragma unroll
        for (int b = 0; b < NBC; b++) {
            float c = sc[r][b];
            o.x = fmaf(c, bas[b].x, o.x); o.y = fmaf(c, bas[b].y, o.y);
            o.z = fmaf(c, bas[b].z, o.z); o.w = fmaf(c, bas[b].w, o.w);
        }
        *reinterpret_cast<float4*>(&g_w[((size_t)r * N_ENTC + n) * DIMC + q * 4]) = o;
    }
}

// ---------------- RGCN scatter: one W row per edge -----------------------------
__global__ __launch_bounds__(256) void k_rgcn_scatter(
    const int* __restrict__ ei, const int* __restrict__ et)
{
    int w = (blockIdx.x * blockDim.x + threadIdx.x) >> 5;
    int lane = threadIdx.x & 31;
    if (w >= E_DBC) return;
    int src = ei[w];
    int dst = ei[E_DBC + w];
    int r   = et[w];
    float4 v = __ldg(reinterpret_cast<const float4*>(
        &g_w[((size_t)r * N_ENTC + src) * DIMC + lane * 4]));
    float* dsta = &g_db_agg[(size_t)dst * DIMC + lane * 4];
    asm volatile("red.global.add.v4.f32 [%0], {%1, %2, %3, %4};"
                 :: "l"(dsta), "f"(v.x), "f"(v.y), "f"(v.z), "f"(v.w)
                 : "memory");
    if (lane == 0) atomicAdd(&g_db_cnt[dst], 1.f);
}

__global__ void k_rgcn_fin(const float* __restrict__ root, const float* __restrict__ bias) {
    int i = blockIdx.x * blockDim.x + threadIdx.x;
    if (i >= N_ENTC * DIMC / 4) return;
    int n = i >> 5, dq = i & 31;
    float inv = 1.f / fmaxf(g_db_cnt[n], 1.f);
    float4 a = reinterpret_cast<const float4*>(g_db_agg)[i];
    float4 r = reinterpret_cast<const float4*>(root)[i];
    float4 bs = reinterpret_cast<const float4*>(bias)[dq];
    float4 o;
    o.x = a.x * inv + r.x + bs.x; o.y = a.y * inv + r.y + bs.y;
    o.z = a.z * inv + r.z + bs.z; o.w = a.w * inv + r.w + bs.w;
    reinterpret_cast<float4*>(g_db_feats)[i] = o;
}

// ---------------- GCN over concepts -------------------------------------------
__global__ void k_deg(const int* __restrict__ cei) {
    int e = blockIdx.x * blockDim.x + threadIdx.x;
    if (e < E_CONC) atomicAdd(&g_deg[cei[E_CONC + e]], 1.f);
}

__global__ void k_dinv() {
    int i = blockIdx.x * blockDim.x + threadIdx.x;
    if (i < N_CONC) g_dinv[i] = rsqrtf(g_deg[i] + 1.0f);
}

#define XR2 32
__global__ __launch_bounds__(128) void k_xw(const float* __restrict__ emb,
                                            const float* __restrict__ W) {
    int g0 = blockIdx.x * XR2;
    int d = threadIdx.x;
    __shared__ __align__(16) float sh[DIMC][XR2];
    int nr = N_CONC - g0; if (nr > XR2) nr = XR2;
#pragma unroll 4
    for (int r = 0; r < XR2; r++)
        sh[d][r] = (r < nr) ? emb[(size_t)(g0 + r) * DIMC + d] : 0.f;
    __syncthreads();
    unsigned long long acc[XR2 / 2];
#pragma unroll
    for (int q = 0; q < XR2 / 2; q++) acc[q] = 0ULL;
#pragma unroll 4
    for (int k = 0; k < DIMC; k++) {
        float w = W[k * DIMC + d];
        unsigned long long wp;
        PACK2(wp, w);
        const ulonglong2* ep = reinterpret_cast<const ulonglong2*>(&sh[k][0]);
#pragma unroll
        for (int q = 0; q < XR2 / 4; q++) {
            ulonglong2 e2 = ep[q];
            FMA2(acc[2 * q],     e2.x, wp);
            FMA2(acc[2 * q + 1], e2.y, wp);
        }
    }
    for (int r = 0; r < nr; r++) {
        unsigned long long v = acc[r >> 1];
        float f = (r & 1) ? __uint_as_float((unsigned)(v >> 32))
                          : __uint_as_float((unsigned)v);
        g_xw[(size_t)(g0 + r) * DIMC + d] = f;
    }
}

__global__ __launch_bounds__(256) void k_gcn_scatter(const int* __restrict__ cei) {
    int w = (blockIdx.x * blockDim.x + threadIdx.x) >> 5;
    int lane = threadIdx.x & 31;
    if (w >= E_CONC) return;
    int s = cei[w];
    int t = cei[E_CONC + w];
    float nm = g_dinv[s] * g_dinv[t];
    const float4* xp = reinterpret_cast<const float4*>(&g_xw[(size_t)s * DIMC]);
    float4 v = __ldg(&xp[lane]);
    float* dsta = &g_con_acc[(size_t)t * DIMC + lane * 4];
    asm volatile("red.global.add.v4.f32 [%0], {%1, %2, %3, %4};"
                 :: "l"(dsta), "f"(nm * v.x), "f"(nm * v.y), "f"(nm * v.z), "f"(nm * v.w)
                 : "memory");
}

__global__ void k_gcn_fin(const float* __restrict__ gb) {
    int i = blockIdx.x * blockDim.x + threadIdx.x;
    if (i >= N_CONC * DIMC / 4) return;
    int n = i >> 5, dq = i & 31;
    float di = g_dinv[n];
    float sl = di * di;
    float4 a = reinterpret_cast<const float4*>(g_con_acc)[i];
    float4 x = reinterpret_cast<const float4*>(g_xw)[i];
    float4 bs = reinterpret_cast<const float4*>(gb)[dq];
    float4 o;
    o.x = a.x + sl * x.x + bs.x; o.y = a.y + sl * x.y + bs.y;
    o.z = a.z + sl * x.z + bs.z; o.w = a.w + sl * x.w + bs.w;
    reinterpret_cast<float4*>(g_con_feats)[i] = o;
}

// ---------------- attention e-scores as tiled GEMM -----------------------------
// templated: feats/eout bound to device globals IN DEVICE CODE (host-side
// __device__-symbol args read the HOST shadow via ATS on GB300 — silent wrong data)
#define EM  64
#define EKC 32
#define EHP 68
#define EAP 132
template<bool DB>
__global__ __launch_bounds__(256, 2) void k_attn_e(
    const int* __restrict__ idxarr,
    const float* __restrict__ A, const float* __restrict__ bv)
{
    const float* feats = DB ? g_db_feats : g_con_feats;
    float* eout = DB ? g_e_db : g_e_con;
    __shared__ __align__(16) float sH[EKC * EHP];
    __shared__ __align__(16) float sA[EKC * EAP];
    int tid = threadIdx.x;
    int tx = tid & 15, ty = tid >> 4;
    int m0 = ty * 4, n0 = tx * 8;
    int bm = blockIdx.x * EM;
    unsigned long long c[4][4];
#pragma unroll
    for (int i = 0; i < 4; i++)
#pragma unroll
        for (int j = 0; j < 4; j++) c[i][j] = 0ULL;

    for (int kc = 0; kc < DIMC; kc += EKC) {
#pragma unroll
        for (int it = 0; it < 2; it++) {
            int idx = tid + it * 256;
            int row = idx >> 3;
            int kq = idx & 7;
            int gi = idxarr[bm + row];
            float4 h = *reinterpret_cast<const float4*>(
                &feats[(size_t)gi * DIMC + kc + kq * 4]);
            int kk = kq * 4;
            sH[(kk + 0) * EHP + row] = h.x; sH[(kk + 1) * EHP + row] = h.y;
            sH[(kk + 2) * EHP + row] = h.z; sH[(kk + 3) * EHP + row] = h.w;
        }
#pragma unroll
        for (int it = 0; it < 4; it++) {
            int idx = tid + it * 256;
            int ar = idx >> 5;
            int ac = idx & 31;
            float4 a = *reinterpret_cast<const float4*>(
                &A[(size_t)(kc + ar) * DIMC + ac * 4]);
            *reinterpret_cast<float4*>(&sA[ar * EAP + ac * 4]) = a;
        }
        __syncthreads();
#pragma unroll 4
        for (int kk = 0; kk < EKC; kk++) {
            float4 h4 = *reinterpret_cast<const float4*>(&sH[kk * EHP + m0]);
            ulonglong2 q0 = *reinterpret_cast<const ulonglong2*>(&sA[kk * EAP + n0]);
            ulonglong2 q1 = *reinterpret_cast<const ulonglong2*>(&sA[kk * EAP + n0 + 4]);
            float hv[4] = {h4.x, h4.y, h4.z, h4.w};
#pragma unroll
            for (int i = 0; i < 4; i++) {
                unsigned long long p;
                PACK2(p, hv[i]);
                FMA2(c[i][0], p, q0.x); FMA2(c[i][1], p, q0.y);
                FMA2(c[i][2], p, q1.x); FMA2(c[i][3], p, q1.y);
            }
        }
        __syncthreads();
    }
    float4 bva = *reinterpret_cast<const float4*>(&bv[n0]);
    float4 bvb = *reinterpret_cast<const float4*>(&bv[n0 + 4]);
    float bb[8] = {bva.x, bva.y, bva.z, bva.w, bvb.x, bvb.y, bvb.z, bvb.w};
#pragma unroll
    for (int i = 0; i < 4; i++) {
        float ep = 0.f;
#pragma unroll
        for (int j = 0; j < 4; j++) {
            float lo = __uint_as_float((unsigned)c[i][j]);
            float hi = __uint_as_float((unsigned)(c[i][j] >> 32));
            ep += tanhf(lo) * bb[2 * j] + tanhf(hi) * bb[2 * j + 1];
        }
#pragma unroll
        for (int o = 8; o; o >>= 1) ep += __shfl_xor_sync(0xffffffffu, ep, o);
        if (tx == 0) eout[bm + m0 + i] = ep;
    }
}

// ---------------- attention finish: softmax + weighted sum ---------------------
__global__ __launch_bounds__(128) void k_attn_fin_db(
    const int* __restrict__ seed_pad, const int* __restrict__ seed_lens)
{
    int b = blockIdx.x, d = threadIdx.x;
    __shared__ float e_sh[SSC], a_sh[SSC];
    __shared__ int idx_sh[SSC];
    int len = seed_lens[b];
    if (d < SSC) {
        e_sh[d] = g_e_db[b * SSC + d];
        idx_sh[d] = seed_pad[b * SSC + d];
    }
    __syncthreads();
    if (d == 0) {
        float m = -3.0e38f;
        float v[SSC];
        for (int s = 0; s < SSC; s++) {
            v[s] = (s < len) ? e_sh[s] : -1e30f;
            m = fmaxf(m, v[s]);
        }
        float Z = 0.f;
        for (int s = 0; s < SSC; s++) { float w = expf(v[s] - m); a_sh[s] = w; Z += w; }
        float inv = 1.f / Z;
        for (int s = 0; s < SSC; s++) a_sh[s] *= inv;
    }
    __syncthreads();
    float du = 0.f;
#pragma unroll 8
    for (int s = 0; s < SSC; s++)
        du += a_sh[s] * g_db_feats[(size_t)idx_sh[s] * DIMC + d];
    if (len <= 0) du = 0.f;
    g_db_user[b * DIMC + d] = du;
    if (d == 0) g_mask[b] = (len > 0) ? 1.f : 0.f;
}

__global__ __launch_bounds__(128) void k_attn_fin_con(const int* __restrict__ cm) {
    int b = blockIdx.x, d = threadIdx.x;
    __shared__ float e_sh[LCC], a_sh[LCC];
    __shared__ int idx_sh[LCC];
    if (d < LCC) {
        e_sh[d] = g_e_con[b * LCC + d];
        idx_sh[d] = cm[b * LCC + d];
    }
    __syncthreads();
    if (d == 0) {
        float m = -3.0e38f;
        float v[LCC];
        for (int s = 0; s < LCC; s++) {
            v[s] = (idx_sh[s] != 0) ? e_sh[s] : -1e30f;
            m = fmaxf(m, v[s]);
        }
        float Z = 0.f;
        for (int s = 0; s < LCC; s++) { float w = expf(v[s] - m); a_sh[s] = w; Z += w; }
        float inv = 1.f / Z;
        for (int s = 0; s < LCC; s++) a_sh[s] *= inv;
    }
    __syncthreads();
    float cu = 0.f;
#pragma unroll 10
    for (int s = 0; s < LCC; s++)
        cu += a_sh[s] * g_con_feats[(size_t)idx_sh[s] * DIMC + d];
    g_con_user[b * DIMC + d] = cu;
}

// ---------------- gated fusion + info projection -------------------------------
__global__ __launch_bounds__(128) void k_fuse(
    const float* __restrict__ unw, const float* __restrict__ unb,
    const float* __restrict__ gw, const float* __restrict__ gb,
    const float* __restrict__ icw, const float* __restrict__ icb)
{
    int b = blockIdx.x, d = threadIdx.x;
    __shared__ __align__(16) float cat[2 * DIMC];
    __shared__ float redv[4];
    __shared__ float sg;
    cat[d] = g_con_user[b * DIMC + d];
    cat[DIMC + d] = g_db_user[b * DIMC + d];
    __syncthreads();
    float u = unb[d];
    {
        const float4* wr = reinterpret_cast<const float4*>(unw + (size_t)d * 2 * DIMC);
        const float4* cp = reinterpret_cast<const float4*>(cat);
#pragma unroll 8
        for (int q = 0; q < (2 * DIMC) / 4; q++) {
            float4 w4 = wr[q]; float4 c4 = cp[q];
            u += w4.x * c4.x + w4.y * c4.y + w4.z * c4.z + w4.w * c4.w;
        }
    }
    float gv = u * gw[d];
    int lane = d & 31, wd = d >> 5;
#pragma unroll
    for (int o = 16; o; o >>= 1) gv += __shfl_down_sync(0xffffffffu, gv, o);
    if (lane == 0) redv[wd] = gv;
    __syncthreads();
    if (d == 0) {
        float s = redv[0] + redv[1] + redv[2] + redv[3] + gb[0];
        sg = 1.f / (1.f + expf(-s));
    }
    __syncthreads();
    float g = sg;
    float cu = cat[d], du = cat[DIMC + d];
    g_user_emb[b * DIMC + d] = g * du + (1.f - g) * cu;
    float ce = icb[d];
    {
        const float4* ir = reinterpret_cast<const float4*>(icw + (size_t)d * DIMC);
        const float4* cp = reinterpret_cast<const float4*>(cat);
#pragma unroll 8
        for (int q = 0; q < DIMC / 4; q++) {
            float4 w4 = ir[q]; float4 c4 = cp[q];
            ce += w4.x * c4.x + w4.y * c4.y + w4.z * c4.z + w4.w * c4.w;
        }
    }
    g_con_e[b * DIMC + d] = ce;
}

// ---------------- fused dual GEMM + softmax partials + MSE --------------------
#define GBM 64
#define GBN 128
#define GKC 32
#define SAP 68
#define SBP 132
__global__ __launch_bounds__(128, 2) void k_score_gemm(
    const float* __restrict__ enb, const float* __restrict__ infb,
    const float* __restrict__ dbvec, float* __restrict__ out, int off)
{
    __shared__ __align__(16) float sA1[GKC * SAP];
    __shared__ __align__(16) float sA2[GKC * SAP];
    __shared__ __align__(16) float sB[GKC * SBP];
    int tid = threadIdx.x;
    int tx = tid & 15, ty = tid >> 4;
    int m0 = ty * 8, n0 = tx * 8;
    int bn = blockIdx.x * GBN, bm = blockIdx.y * GBM;
    unsigned long long c1[8][4], c2[8][4];
#pragma unroll
    for (int i = 0; i < 8; i++)
#pragma unroll
        for (int j = 0; j < 4; j++) { c1[i][j] = 0ULL; c2[i][j] = 0ULL; }

    for (int kc = 0; kc < DIMC; kc += GKC) {
#pragma unroll
        for (int it = 0; it < 4; it++) {
            int idx = tid + it * 128;
            int row = idx >> 3;
            int kq = idx & 7;
            float4 a1 = *reinterpret_cast<const float4*>(
                &g_user_emb[(size_t)(bm + row) * DIMC + kc + kq * 4]);
            float4 a2 = *reinterpret_cast<const float4*>(
                &g_con_e[(size_t)(bm + row) * DIMC + kc + kq * 4]);
            int kk = kq * 4;
            sA1[(kk + 0) * SAP + row] = a1.x; sA1[(kk + 1) * SAP + row] = a1.y;
            sA1[(kk + 2) * SAP + row] = a1.z; sA1[(kk + 3) * SAP + row] = a1.w;
            sA2[(kk + 0) * SAP + row] = a2.x; sA2[(kk + 1) * SAP + row] = a2.y;
            sA2[(kk + 2) * SAP + row] = a2.z; sA2[(kk + 3) * SAP + row] = a2.w;
        }
#pragma unroll
        for (int it = 0; it < 8; it++) {
            int idx = tid + it * 128;
            int row = idx >> 3;
            int kq = idx & 7;
            int gn = bn + row;
            float4 bb = make_float4(0.f, 0.f, 0.f, 0.f);
            if (gn < N_ENTC)
                bb = *reinterpret_cast<const float4*>(
                    &g_db_feats[(size_t)gn * DIMC + kc + kq * 4]);
            int kk = kq * 4;
            sB[(kk + 0) * SBP + row] = bb.x; sB[(kk + 1) * SBP + row] = bb.y;
            sB[(kk + 2) * SBP + row] = bb.z; sB[(kk + 3) * SBP + row] = bb.w;
        }
        __syncthreads();
#pragma unroll 4
        for (int kk = 0; kk < GKC; kk++) {
            float4 a1lo = *reinterpret_cast<const float4*>(&sA1[kk * SAP + m0]);
            float4 a1hi = *reinterpret_cast<const float4*>(&sA1[kk * SAP + m0 + 4]);
            float4 a2lo = *reinterpret_cast<const float4*>(&sA2[kk * SAP + m0]);
            float4 a2hi = *reinterpret_cast<const float4*>(&sA2[kk * SAP + m0 + 4]);
            ulonglong2 q0 = *reinterpret_cast<const ulonglong2*>(&sB[kk * SBP + n0]);
            ulonglong2 q1 = *reinterpret_cast<const ulonglong2*>(&sB[kk * SBP + n0 + 4]);
            unsigned long long b0 = q0.x, b1 = q0.y, b2 = q1.x, b3 = q1.y;
            float av1[8] = {a1lo.x, a1lo.y, a1lo.z, a1lo.w, a1hi.x, a1hi.y, a1hi.z, a1hi.w};
            float av2[8] = {a2lo.x, a2lo.y, a2lo.z, a2lo.w, a2hi.x, a2hi.y, a2hi.z, a2hi.w};
#pragma unroll
            for (int i = 0; i < 8; i++) {
                unsigned long long p1, p2;
                PACK2(p1, av1[i]);
                PACK2(p2, av2[i]);
                FMA2(c1[i][0], p1, b0); FMA2(c1[i][1], p1, b1);
                FMA2(c1[i][2], p1, b2); FMA2(c1[i][3], p1, b3);
                FMA2(c2[i][0], p2, b0); FMA2(c2[i][1], p2, b1);
                FMA2(c2[i][2], p2, b2); FMA2(c2[i][3], p2, b3);
            }
        }
        __syncthreads();
    }

    bool tail = (bn + GBN > N_ENTC);
    float* orow_base = out + off;
#pragma unroll
    for (int i = 0; i < 8; i++) {
        int gm = bm + m0 + i;
        float es[8], dd[8];
#pragma unroll
        for (int j = 0; j < 4; j++) {
            es[2 * j]     = __uint_as_float((unsigned)c1[i][j]);
            es[2 * j + 1] = __uint_as_float((unsigned)(c1[i][j] >> 32));
            dd[2 * j]     = __uint_as_float((unsigned)c2[i][j]);
            dd[2 * j + 1] = __uint_as_float((unsigned)(c2[i][j] >> 32));
        }
        float mx = -3.0e38f, sq = 0.f;
        float* orow = orow_base + (size_t)gm * N_ENTC + bn + n0;
        if (!tail) {
            float4 e4a = *reinterpret_cast<const float4*>(&enb[bn + n0]);
            float4 e4b = *reinterpret_cast<const float4*>(&enb[bn + n0 + 4]);
            float4 i4a = *reinterpret_cast<const float4*>(&infb[bn + n0]);
            float4 i4b = *reinterpret_cast<const float4*>(&infb[bn + n0 + 4]);
            float4 v4a = *reinterpret_cast<const float4*>(&dbvec[(size_t)gm * N_ENTC + bn + n0]);
            float4 v4b = *reinterpret_cast<const float4*>(&dbvec[(size_t)gm * N_ENTC + bn + n0 + 4]);
            float eb[8] = {e4a.x, e4a.y, e4a.z, e4a.w, e4b.x, e4b.y, e4b.z, e4b.w};
            float ib[8] = {i4a.x, i4a.y, i4a.z, i4a.w, i4b.x, i4b.y, i4b.z, i4b.w};
            float vv[8] = {v4a.x, v4a.y, v4a.z, v4a.w, v4b.x, v4b.y, v4b.z, v4b.w};
#pragma unroll
            for (int j = 0; j < 8; j++) {
                es[j] += eb[j];
                mx = fmaxf(mx, es[j]);
                float df = dd[j] + ib[j] - vv[j];
                sq += df * df;
                orow[j] = es[j];
            }
        } else {
#pragma unroll
            for (int j = 0; j < 8; j++) {
                int gn = bn + n0 + j;
                if (gn < N_ENTC) {
                    es[j] += enb[gn];
                    mx = fmaxf(mx, es[j]);
                    float df = dd[j] + infb[gn] - dbvec[(size_t)gm * N_ENTC + gn];
                    sq += df * df;
                    orow[j] = es[j];
                } else {
                    es[j] = -3.0e38f;
                }
            }
        }
#pragma unroll
        for (int o = 8; o; o >>= 1) mx = fmaxf(mx, __shfl_xor_sync(0xffffffffu, mx, o));
        float z = 0.f;
#pragma unroll
        for (int j = 0; j < 8; j++) z += __expf(es[j] - mx);
#pragma unroll
        for (int o = 8; o; o >>= 1) {
            z  += __shfl_xor_sync(0xffffffffu, z, o);
            sq += __shfl_xor_sync(0xffffffffu, sq, o);
        }
        if (tx == 0) {
            g_pm[gm * PML + blockIdx.x] = mx;
            g_pz[gm * PML + blockIdx.x] = z;
            atomicAdd(&g_info_partial[gm], sq);
        }
    }
}

// ---------------- softmax partial reduce ---------------------------------------
__global__ __launch_bounds__(256) void k_stats_reduce() {
    int b = blockIdx.x, t = threadIdx.x;
    __shared__ float sm[256], sz[256];
    float m = (t < NBLKN) ? g_pm[b * PML + t] : -3.0e38f;
    sm[t] = m;
    __syncthreads();
    for (int o = 128; o; o >>= 1) {
        if (t < o) sm[t] = fmaxf(sm[t], sm[t + o]);
        __syncthreads();
    }
    float M = sm[0];
    float z = (t < NBLKN) ? g_pz[b * PML + t] * __expf(m - M) : 0.f;
    sz[t] = z;
    __syncthreads();
    for (int o = 128; o; o >>= 1) {
        if (t < o) sz[t] += sz[t + o];
        __syncthreads();
    }
    if (t == 0) { g_bmax[b] = M; g_bZ[b] = sz[0]; }
}

// ---------------- final loss ----------------------------------------------------
__global__ __launch_bounds__(256) void k_final(
    const int* __restrict__ labels, const float* __restrict__ rec,
    float* __restrict__ out, int off)
{
    int b = threadIdx.x;
    int lab = labels[b];
    if (lab < 0) lab = 0;
    if (lab >= N_ENTC) lab = N_ENTC - 1;
    float es = out[off + (size_t)b * N_ENTC + lab];
    float ce = (g_bmax[b] + logf(g_bZ[b])) - es;
    float rv = ce * rec[b];
    float iv = g_info_partial[b] * g_mask[b];
    __shared__ float s1[256], s2[256];
    s1[b] = rv; s2[b] = iv;
    __syncthreads();
    for (int o = 128; o; o >>= 1) {
        if (b < o) { s1[b] += s1[b + o]; s2[b] += s2[b + o]; }
        __syncthreads();
    }
    if (b == 0) {
        float rl = s1[0];
        float loss = rl + 0.025f * (s2[0] / (float)BBC);
        if (off) {
            out[0] = loss;
            out[1 + (size_t)BBC * N_ENTC] = rl;
        }
    }
}

// ---------------- launch ---------------------------------------------------------
extern "C" void kernel_launch(void* const* d_in, const int* in_sizes, int n_in,
                              void* d_out, int out_size) {
    const int*   concept_mask = (const int*)d_in[0];
    const int*   seed_pad     = (const int*)d_in[1];
    const int*   seed_lens    = (const int*)d_in[2];
    const int*   db_ei        = (const int*)d_in[3];
    const int*   db_et        = (const int*)d_in[4];
    const int*   con_ei       = (const int*)d_in[5];
    const float* db_vec       = (const float*)d_in[6];
    const int*   labels       = (const int*)d_in[7];
    const float* rec          = (const float*)d_in[8];
    const float* concept_emb  = (const float*)d_in[9];
    const float* basis        = (const float*)d_in[10];
    const float* comp         = (const float*)d_in[11];
    const float* rgcn_root    = (const float*)d_in[12];
    const float* rgcn_bias    = (const float*)d_in[13];
    const float* gcn_w        = (const float*)d_in[14];
    const float* gcn_b        = (const float*)d_in[15];
    const float* attn_a       = (const float*)d_in[16];
    const float* attn_b       = (const float*)d_in[17];
    const float* attn_a_db    = (const float*)d_in[18];
    const float* attn_b_db    = (const float*)d_in[19];
    const float* user_norm_w  = (const float*)d_in[20];
    const float* user_norm_b  = (const float*)d_in[21];
    const float* gate_norm_w  = (const float*)d_in[22];
    const float* gate_norm_b  = (const float*)d_in[23];
    const float* info_con_w   = (const float*)d_in[24];
    const float* info_con_b   = (const float*)d_in[25];
    const float* info_out_db_b= (const float*)d_in[26];
    const float* output_en_b  = (const float*)d_in[27];
    float* out = (float*)d_out;

    long long total = (long long)BBC * N_ENTC;
    int off = ((long long)out_size >= total + 2) ? 1 : 0;

    static cudaStream_t s1 = nullptr, s2 = nullptr;
    static cudaEvent_t eF = nullptr, eZ = nullptr, eJ1 = nullptr, eJ2 = nullptr;
    if (s1 == nullptr) {
        cudaStreamCreateWithFlags(&s1, cudaStreamNonBlocking);
        cudaStreamCreateWithFlags(&s2, cudaStreamNonBlocking);
        cudaEventCreateWithFlags(&eF, cudaEventDisableTiming);
        cudaEventCreateWithFlags(&eZ, cudaEventDisableTiming);
        cudaEventCreateWithFlags(&eJ1, cudaEventDisableTiming);
        cudaEventCreateWithFlags(&eJ2, cudaEventDisableTiming);
    }

    // fork s1 immediately: wbuild is independent of the zero pass
    cudaEventRecord(eF, 0);
    cudaStreamWaitEvent(s1, eF, 0);
    k_wbuild<<<(N_ENTC * 32 + 255) / 256, 256, 0, s1>>>(comp, basis);

    // zero runs concurrently on default stream
    k_zero<<<3750, 256>>>();
    cudaEventRecord(eZ, 0);
    cudaStreamWaitEvent(s1, eZ, 0);
    cudaStreamWaitEvent(s2, eZ, 0);

    // chain 1: RGCN/db path
    k_rgcn_scatter<<<(E_DBC * 32 + 255) / 256, 256, 0, s1>>>(db_ei, db_et);
    k_rgcn_fin<<<(N_ENTC * DIMC / 4 + 255) / 256, 256, 0, s1>>>(rgcn_root, rgcn_bias);
    k_attn_e<true><<<BBC * SSC / EM, 256, 0, s1>>>(seed_pad, attn_a_db, attn_b_db);
    k_attn_fin_db<<<BBC, 128, 0, s1>>>(seed_pad, seed_lens);

    // chain 2: GCN/concept path
    k_deg<<<(E_CONC + 255) / 256, 256, 0, s2>>>(con_ei);
    k_dinv<<<(N_CONC + 255) / 256, 256, 0, s2>>>();
    k_xw<<<(N_CONC + XR2 - 1) / XR2, 128, 0, s2>>>(concept_emb, gcn_w);
    k_gcn_scatter<<<(E_CONC * 32 + 255) / 256, 256, 0, s2>>>(con_ei);
    k_gcn_fin<<<(N_CONC * DIMC / 4 + 255) / 256, 256, 0, s2>>>(gcn_b);
    k_attn_e<false><<<BBC * LCC / EM, 256, 0, s2>>>(concept_mask, attn_a, attn_b);
    k_attn_fin_con<<<BBC, 128, 0, s2>>>(concept_mask);

    cudaEventRecord(eJ1, s1);
    cudaEventRecord(eJ2, s2);
    cudaStreamWaitEvent(0, eJ1, 0);
    cudaStreamWaitEvent(0, eJ2, 0);

    k_fuse<<<BBC, 128>>>(user_norm_w, user_norm_b, gate_norm_w, gate_norm_b,
                         info_con_w, info_con_b);
    dim3 gg(NBLKN, BBC / GBM);
    k_score_gemm<<<gg, 128>>>(output_en_b, info_out_db_b, db_vec, out, off);
    k_stats_reduce<<<BBC, 256>>>();
    k_final<<<1, 256>>>(labels, rec, out, off);
}

// round 11
// speedup vs baseline: 1.1453x; 1.0484x over previous
#include <cuda_runtime.h>
#include <cuda_bf16.h>
#include <math.h>
#include <stdint.h>

#define N_ENTC 30000
#define N_CONC 29309
#define DIMC   128
#define NBC    8
#define RC     12
#define BBC    256
#define LCC    50
#define SSC    32
#define E_DBC  300000
#define E_CONC 200000
#define NBLKN  235
#define PML    240

// ---------------- scratch ----------------------------------------------------
__device__ __align__(16) __nv_bfloat16 g_w[(size_t)RC * N_ENTC * DIMC];  // 92MB bf16
__device__ __align__(16) float g_db_agg[N_ENTC * DIMC];
__device__ __align__(16) float g_db_cnt[N_ENTC];
__device__ __align__(16) float g_db_feats[N_ENTC * DIMC];
__device__ __align__(16) float g_xw[N_CONC * DIMC];
__device__ __align__(16) float g_con_acc[N_CONC * DIMC];
__device__ __align__(16) float g_con_feats[N_CONC * DIMC];
__device__ __align__(16) float g_deg[29312];
__device__ __align__(16) float g_dinv[29312];
__device__ __align__(16) float g_e_db[BBC * SSC];
__device__ __align__(16) float g_e_con[BBC * LCC];
__device__ __align__(16) float g_db_user[BBC * DIMC];
__device__ __align__(16) float g_con_user[BBC * DIMC];
__device__ __align__(16) float g_mask[BBC];
__device__ __align__(16) float g_user_emb[BBC * DIMC];
__device__ __align__(16) float g_con_e[BBC * DIMC];
__device__ __align__(16) float g_info_partial[BBC];
__device__ __align__(16) float g_bmax[BBC];
__device__ __align__(16) float g_bZ[BBC];
__device__ __align__(16) float g_pm[BBC * PML];
__device__ __align__(16) float g_pz[BBC * PML];

#define FMA2(c, a, b) asm("fma.rn.f32x2 %0, %1, %2, %0;" : "+l"(c) : "l"(a), "l"(b))
#define PACK2(d, f)   asm("mov.b64 %0, {%1, %1};" : "=l"(d) : "f"(f))

// ---------------- zero scratch ------------------------------------------------
__global__ void k_zero() {
    int i = blockIdx.x * blockDim.x + threadIdx.x;
    float4 z = make_float4(0.f, 0.f, 0.f, 0.f);
    if (i < N_ENTC * DIMC / 4) reinterpret_cast<float4*>(g_db_agg)[i] = z;
    if (i < N_CONC * DIMC / 4) reinterpret_cast<float4*>(g_con_acc)[i] = z;
    if (i < N_ENTC / 4)        reinterpret_cast<float4*>(g_db_cnt)[i] = z;
    if (i < 29312 / 4)         reinterpret_cast<float4*>(g_deg)[i] = z;
    if (i < BBC / 4)           reinterpret_cast<float4*>(g_info_partial)[i] = z;
}

// ---------------- W = einsum('rb,bnd->rnd', comp, basis)  -> bf16 --------------
__global__ __launch_bounds__(256) void k_wbuild(
    const float* __restrict__ comp, const float* __restrict__ basis)
{
    __shared__ float sc[RC][NBC];
    int tid = threadIdx.x;
    if (tid < RC * NBC) ((float*)sc)[tid] = comp[tid];
    __syncthreads();
    int i = blockIdx.x * 256 + tid;
    if (i >= N_ENTC * 32) return;
    int n = i >> 5, q = i & 31;
    float4 bas[NBC];
#pragma unroll
    for (int b = 0; b < NBC; b++)
        bas[b] = __ldg(reinterpret_cast<const float4*>(
            &basis[((size_t)b * N_ENTC + n) * DIMC + q * 4]));
#pragma unroll
    for (int r = 0; r < RC; r++) {
        float4 o = make_float4(0.f, 0.f, 0.f, 0.f);
#pragma unroll
        for (int b = 0; b < NBC; b++) {
            float c = sc[r][b];
            o.x = fmaf(c, bas[b].x, o.x); o.y = fmaf(c, bas[b].y, o.y);
            o.z = fmaf(c, bas[b].z, o.z); o.w = fmaf(c, bas[b].w, o.w);
        }
        union { unsigned long long u; __nv_bfloat162 h[2]; } w;
        w.h[0] = __floats2bfloat162_rn(o.x, o.y);
        w.h[1] = __floats2bfloat162_rn(o.z, o.w);
        *reinterpret_cast<unsigned long long*>(
            &g_w[((size_t)r * N_ENTC + n) * DIMC + q * 4]) = w.u;
    }
}

// ---------------- RGCN scatter: one bf16 W row per edge ------------------------
__global__ __launch_bounds__(256) void k_rgcn_scatter(
    const int* __restrict__ ei, const int* __restrict__ et)
{
    int w = (blockIdx.x * blockDim.x + threadIdx.x) >> 5;
    int lane = threadIdx.x & 31;
    if (w >= E_DBC) return;
    int src = ei[w];
    int dst = ei[E_DBC + w];
    int r   = et[w];
    const unsigned long long* wr = reinterpret_cast<const unsigned long long*>(
        &g_w[((size_t)r * N_ENTC + src) * DIMC]);
    union { unsigned long long u; __nv_bfloat162 h[2]; } v;
    v.u = __ldg(&wr[lane]);
    float2 f0 = __bfloat1622float2(v.h[0]);
    float2 f1 = __bfloat1622float2(v.h[1]);
    float* dsta = &g_db_agg[(size_t)dst * DIMC + lane * 4];
    asm volatile("red.global.add.v4.f32 [%0], {%1, %2, %3, %4};"
                 :: "l"(dsta), "f"(f0.x), "f"(f0.y), "f"(f1.x), "f"(f1.y) : "memory");
    if (lane == 0) atomicAdd(&g_db_cnt[dst], 1.f);
}

__global__ void k_rgcn_fin(const float* __restrict__ root, const float* __restrict__ bias) {
    int i = blockIdx.x * blockDim.x + threadIdx.x;
    if (i >= N_ENTC * DIMC / 4) return;
    int n = i >> 5, dq = i & 31;
    float inv = 1.f / fmaxf(g_db_cnt[n], 1.f);
    float4 a = reinterpret_cast<const float4*>(g_db_agg)[i];
    float4 r = reinterpret_cast<const float4*>(root)[i];
    float4 bs = reinterpret_cast<const float4*>(bias)[dq];
    float4 o;
    o.x = a.x * inv + r.x + bs.x; o.y = a.y * inv + r.y + bs.y;
    o.z = a.z * inv + r.z + bs.z; o.w = a.w * inv + r.w + bs.w;
    reinterpret_cast<float4*>(g_db_feats)[i] = o;
}

// ---------------- GCN over concepts -------------------------------------------
__global__ void k_deg(const int* __restrict__ cei) {
    int e = blockIdx.x * blockDim.x + threadIdx.x;
    if (e < E_CONC) atomicAdd(&g_deg[cei[E_CONC + e]], 1.f);
}

__global__ void k_dinv() {
    int i = blockIdx.x * blockDim.x + threadIdx.x;
    if (i < N_CONC) g_dinv[i] = rsqrtf(g_deg[i] + 1.0f);
}

#define XR2 32
__global__ __launch_bounds__(128) void k_xw(const float* __restrict__ emb,
                                            const float* __restrict__ W) {
    int g0 = blockIdx.x * XR2;
    int d = threadIdx.x;
    __shared__ __align__(16) float sh[DIMC][XR2];
    int nr = N_CONC - g0; if (nr > XR2) nr = XR2;
#pragma unroll 4
    for (int r = 0; r < XR2; r++)
        sh[d][r] = (r < nr) ? emb[(size_t)(g0 + r) * DIMC + d] : 0.f;
    __syncthreads();
    unsigned long long acc[XR2 / 2];
#pragma unroll
    for (int q = 0; q < XR2 / 2; q++) acc[q] = 0ULL;
#pragma unroll 4
    for (int k = 0; k < DIMC; k++) {
        float w = W[k * DIMC + d];
        unsigned long long wp;
        PACK2(wp, w);
        const ulonglong2* ep = reinterpret_cast<const ulonglong2*>(&sh[k][0]);
#pragma unroll
        for (int q = 0; q < XR2 / 4; q++) {
            ulonglong2 e2 = ep[q];
            FMA2(acc[2 * q],     e2.x, wp);
            FMA2(acc[2 * q + 1], e2.y, wp);
        }
    }
    for (int r = 0; r < nr; r++) {
        unsigned long long v = acc[r >> 1];
        float f = (r & 1) ? __uint_as_float((unsigned)(v >> 32))
                          : __uint_as_float((unsigned)v);
        g_xw[(size_t)(g0 + r) * DIMC + d] = f;
    }
}

__global__ __launch_bounds__(256) void k_gcn_scatter(const int* __restrict__ cei) {
    int w = (blockIdx.x * blockDim.x + threadIdx.x) >> 5;
    int lane = threadIdx.x & 31;
    if (w >= E_CONC) return;
    int s = cei[w];
    int t = cei[E_CONC + w];
    float nm = g_dinv[s] * g_dinv[t];
    const float4* xp = reinterpret_cast<const float4*>(&g_xw[(size_t)s * DIMC]);
    float4 v = __ldg(&xp[lane]);
    float* dsta = &g_con_acc[(size_t)t * DIMC + lane * 4];
    asm volatile("red.global.add.v4.f32 [%0], {%1, %2, %3, %4};"
                 :: "l"(dsta), "f"(nm * v.x), "f"(nm * v.y), "f"(nm * v.z), "f"(nm * v.w)
                 : "memory");
}

__global__ void k_gcn_fin(const float* __restrict__ gb) {
    int i = blockIdx.x * blockDim.x + threadIdx.x;
    if (i >= N_CONC * DIMC / 4) return;
    int n = i >> 5, dq = i & 31;
    float di = g_dinv[n];
    float sl = di * di;
    float4 a = reinterpret_cast<const float4*>(g_con_acc)[i];
    float4 x = reinterpret_cast<const float4*>(g_xw)[i];
    float4 bs = reinterpret_cast<const float4*>(gb)[dq];
    float4 o;
    o.x = a.x + sl * x.x + bs.x; o.y = a.y + sl * x.y + bs.y;
    o.z = a.z + sl * x.z + bs.z; o.w = a.w + sl * x.w + bs.w;
    reinterpret_cast<float4*>(g_con_feats)[i] = o;
}

// ---------------- attention e-scores as tiled GEMM -----------------------------
#define EM  64
#define EKC 32
#define EHP 68
#define EAP 132
template<bool DB>
__global__ __launch_bounds__(256, 2) void k_attn_e(
    const int* __restrict__ idxarr,
    const float* __restrict__ A, const float* __restrict__ bv)
{
    const float* feats = DB ? g_db_feats : g_con_feats;
    float* eout = DB ? g_e_db : g_e_con;
    __shared__ __align__(16) float sH[EKC * EHP];
    __shared__ __align__(16) float sA[EKC * EAP];
    int tid = threadIdx.x;
    int tx = tid & 15, ty = tid >> 4;
    int m0 = ty * 4, n0 = tx * 8;
    int bm = blockIdx.x * EM;
    unsigned long long c[4][4];
#pragma unroll
    for (int i = 0; i < 4; i++)
#pragma unroll
        for (int j = 0; j < 4; j++) c[i][j] = 0ULL;

    for (int kc = 0; kc < DIMC; kc += EKC) {
#pragma unroll
        for (int it = 0; it < 2; it++) {
            int idx = tid + it * 256;
            int row = idx >> 3;
            int kq = idx & 7;
            int gi = idxarr[bm + row];
            float4 h = *reinterpret_cast<const float4*>(
                &feats[(size_t)gi * DIMC + kc + kq * 4]);
            int kk = kq * 4;
            sH[(kk + 0) * EHP + row] = h.x; sH[(kk + 1) * EHP + row] = h.y;
            sH[(kk + 2) * EHP + row] = h.z; sH[(kk + 3) * EHP + row] = h.w;
        }
#pragma unroll
        for (int it = 0; it < 4; it++) {
            int idx = tid + it * 256;
            int ar = idx >> 5;
            int ac = idx & 31;
            float4 a = *reinterpret_cast<const float4*>(
                &A[(size_t)(kc + ar) * DIMC + ac * 4]);
            *reinterpret_cast<float4*>(&sA[ar * EAP + ac * 4]) = a;
        }
        __syncthreads();
#pragma unroll 4
        for (int kk = 0; kk < EKC; kk++) {
            float4 h4 = *reinterpret_cast<const float4*>(&sH[kk * EHP + m0]);
            ulonglong2 q0 = *reinterpret_cast<const ulonglong2*>(&sA[kk * EAP + n0]);
            ulonglong2 q1 = *reinterpret_cast<const ulonglong2*>(&sA[kk * EAP + n0 + 4]);
            float hv[4] = {h4.x, h4.y, h4.z, h4.w};
#pragma unroll
            for (int i = 0; i < 4; i++) {
                unsigned long long p;
                PACK2(p, hv[i]);
                FMA2(c[i][0], p, q0.x); FMA2(c[i][1], p, q0.y);
                FMA2(c[i][2], p, q1.x); FMA2(c[i][3], p, q1.y);
            }
        }
        __syncthreads();
    }
    float4 bva = *reinterpret_cast<const float4*>(&bv[n0]);
    float4 bvb = *reinterpret_cast<const float4*>(&bv[n0 + 4]);
    float bb[8] = {bva.x, bva.y, bva.z, bva.w, bvb.x, bvb.y, bvb.z, bvb.w};
#pragma unroll
    for (int i = 0; i < 4; i++) {
        float ep = 0.f;
#pragma unroll
        for (int j = 0; j < 4; j++) {
            float lo = __uint_as_float((unsigned)c[i][j]);
            float hi = __uint_as_float((unsigned)(c[i][j] >> 32));
            ep += tanhf(lo) * bb[2 * j] + tanhf(hi) * bb[2 * j + 1];
        }
#pragma unroll
        for (int o = 8; o; o >>= 1) ep += __shfl_xor_sync(0xffffffffu, ep, o);
        if (tx == 0) eout[bm + m0 + i] = ep;
    }
}

// ---------------- attention finish ---------------------------------------------
__global__ __launch_bounds__(128) void k_attn_fin_db(
    const int* __restrict__ seed_pad, const int* __restrict__ seed_lens)
{
    int b = blockIdx.x, d = threadIdx.x;
    __shared__ float e_sh[SSC], a_sh[SSC];
    __shared__ int idx_sh[SSC];
    int len = seed_lens[b];
    if (d < SSC) {
        e_sh[d] = g_e_db[b * SSC + d];
        idx_sh[d] = seed_pad[b * SSC + d];
    }
    __syncthreads();
    if (d == 0) {
        float m = -3.0e38f;
        float v[SSC];
        for (int s = 0; s < SSC; s++) {
            v[s] = (s < len) ? e_sh[s] : -1e30f;
            m = fmaxf(m, v[s]);
        }
        float Z = 0.f;
        for (int s = 0; s < SSC; s++) { float w = expf(v[s] - m); a_sh[s] = w; Z += w; }
        float inv = 1.f / Z;
        for (int s = 0; s < SSC; s++) a_sh[s] *= inv;
    }
    __syncthreads();
    float du = 0.f;
#pragma unroll 8
    for (int s = 0; s < SSC; s++)
        du += a_sh[s] * g_db_feats[(size_t)idx_sh[s] * DIMC + d];
    if (len <= 0) du = 0.f;
    g_db_user[b * DIMC + d] = du;
    if (d == 0) g_mask[b] = (len > 0) ? 1.f : 0.f;
}

__global__ __launch_bounds__(128) void k_attn_fin_con(const int* __restrict__ cm) {
    int b = blockIdx.x, d = threadIdx.x;
    __shared__ float e_sh[LCC], a_sh[LCC];
    __shared__ int idx_sh[LCC];
    if (d < LCC) {
        e_sh[d] = g_e_con[b * LCC + d];
        idx_sh[d] = cm[b * LCC + d];
    }
    __syncthreads();
    if (d == 0) {
        float m = -3.0e38f;
        float v[LCC];
        for (int s = 0; s < LCC; s++) {
            v[s] = (idx_sh[s] != 0) ? e_sh[s] : -1e30f;
            m = fmaxf(m, v[s]);
        }
        float Z = 0.f;
        for (int s = 0; s < LCC; s++) { float w = expf(v[s] - m); a_sh[s] = w; Z += w; }
        float inv = 1.f / Z;
        for (int s = 0; s < LCC; s++) a_sh[s] *= inv;
    }
    __syncthreads();
    float cu = 0.f;
#pragma unroll 10
    for (int s = 0; s < LCC; s++)
        cu += a_sh[s] * g_con_feats[(size_t)idx_sh[s] * DIMC + d];
    g_con_user[b * DIMC + d] = cu;
}

// ---------------- gated fusion + info projection -------------------------------
__global__ __launch_bounds__(128) void k_fuse(
    const float* __restrict__ unw, const float* __restrict__ unb,
    const float* __restrict__ gw, const float* __restrict__ gb,
    const float* __restrict__ icw, const float* __restrict__ icb)
{
    int b = blockIdx.x, d = threadIdx.x;
    __shared__ __align__(16) float cat[2 * DIMC];
    __shared__ float redv[4];
    __shared__ float sg;
    cat[d] = g_con_user[b * DIMC + d];
    cat[DIMC + d] = g_db_user[b * DIMC + d];
    __syncthreads();
    float u = unb[d];
    {
        const float4* wr = reinterpret_cast<const float4*>(unw + (size_t)d * 2 * DIMC);
        const float4* cp = reinterpret_cast<const float4*>(cat);
#pragma unroll 8
        for (int q = 0; q < (2 * DIMC) / 4; q++) {
            float4 w4 = wr[q]; float4 c4 = cp[q];
            u += w4.x * c4.x + w4.y * c4.y + w4.z * c4.z + w4.w * c4.w;
        }
    }
    float gv = u * gw[d];
    int lane = d & 31, wd = d >> 5;
#pragma unroll
    for (int o = 16; o; o >>= 1) gv += __shfl_down_sync(0xffffffffu, gv, o);
    if (lane == 0) redv[wd] = gv;
    __syncthreads();
    if (d == 0) {
        float s = redv[0] + redv[1] + redv[2] + redv[3] + gb[0];
        sg = 1.f / (1.f + expf(-s));
    }
    __syncthreads();
    float g = sg;
    float cu = cat[d], du = cat[DIMC + d];
    g_user_emb[b * DIMC + d] = g * du + (1.f - g) * cu;
    float ce = icb[d];
    {
        const float4* ir = reinterpret_cast<const float4*>(icw + (size_t)d * DIMC);
        const float4* cp = reinterpret_cast<const float4*>(cat);
#pragma unroll 8
        for (int q = 0; q < DIMC / 4; q++) {
            float4 w4 = ir[q]; float4 c4 = cp[q];
            ce += w4.x * c4.x + w4.y * c4.y + w4.z * c4.z + w4.w * c4.w;
        }
    }
    g_con_e[b * DIMC + d] = ce;
}

// ---------------- fused dual GEMM + softmax partials + MSE --------------------
#define GBM 64
#define GBN 128
#define GKC 32
#define SAP 68
#define SBP 132
__global__ __launch_bounds__(128, 2) void k_score_gemm(
    const float* __restrict__ enb, const float* __restrict__ infb,
    const float* __restrict__ dbvec, float* __restrict__ out, int off)
{
    __shared__ __align__(16) float sA1[GKC * SAP];
    __shared__ __align__(16) float sA2[GKC * SAP];
    __shared__ __align__(16) float sB[GKC * SBP];
    int tid = threadIdx.x;
    int tx = tid & 15, ty = tid >> 4;
    int m0 = ty * 8, n0 = tx * 8;
    int bn = blockIdx.x * GBN, bm = blockIdx.y * GBM;
    unsigned long long c1[8][4], c2[8][4];
#pragma unroll
    for (int i = 0; i < 8; i++)
#pragma unroll
        for (int j = 0; j < 4; j++) { c1[i][j] = 0ULL; c2[i][j] = 0ULL; }

    for (int kc = 0; kc < DIMC; kc += GKC) {
#pragma unroll
        for (int it = 0; it < 4; it++) {
            int idx = tid + it * 128;
            int row = idx >> 3;
            int kq = idx & 7;
            float4 a1 = *reinterpret_cast<const float4*>(
                &g_user_emb[(size_t)(bm + row) * DIMC + kc + kq * 4]);
            float4 a2 = *reinterpret_cast<const float4*>(
                &g_con_e[(size_t)(bm + row) * DIMC + kc + kq * 4]);
            int kk = kq * 4;
            sA1[(kk + 0) * SAP + row] = a1.x; sA1[(kk + 1) * SAP + row] = a1.y;
            sA1[(kk + 2) * SAP + row] = a1.z; sA1[(kk + 3) * SAP + row] = a1.w;
            sA2[(kk + 0) * SAP + row] = a2.x; sA2[(kk + 1) * SAP + row] = a2.y;
            sA2[(kk + 2) * SAP + row] = a2.z; sA2[(kk + 3) * SAP + row] = a2.w;
        }
#pragma unroll
        for (int it = 0; it < 8; it++) {
            int idx = tid + it * 128;
            int row = idx >> 3;
            int kq = idx & 7;
            int gn = bn + row;
            float4 bb = make_float4(0.f, 0.f, 0.f, 0.f);
            if (gn < N_ENTC)
                bb = *reinterpret_cast<const float4*>(
                    &g_db_feats[(size_t)gn * DIMC + kc + kq * 4]);
            int kk = kq * 4;
            sB[(kk + 0) * SBP + row] = bb.x; sB[(kk + 1) * SBP + row] = bb.y;
            sB[(kk + 2) * SBP + row] = bb.z; sB[(kk + 3) * SBP + row] = bb.w;
        }
        __syncthreads();
#pragma unroll 4
        for (int kk = 0; kk < GKC; kk++) {
            float4 a1lo = *reinterpret_cast<const float4*>(&sA1[kk * SAP + m0]);
            float4 a1hi = *reinterpret_cast<const float4*>(&sA1[kk * SAP + m0 + 4]);
            float4 a2lo = *reinterpret_cast<const float4*>(&sA2[kk * SAP + m0]);
            float4 a2hi = *reinterpret_cast<const float4*>(&sA2[kk * SAP + m0 + 4]);
            ulonglong2 q0 = *reinterpret_cast<const ulonglong2*>(&sB[kk * SBP + n0]);
            ulonglong2 q1 = *reinterpret_cast<const ulonglong2*>(&sB[kk * SBP + n0 + 4]);
            unsigned long long b0 = q0.x, b1 = q0.y, b2 = q1.x, b3 = q1.y;
            float av1[8] = {a1lo.x, a1lo.y, a1lo.z, a1lo.w, a1hi.x, a1hi.y, a1hi.z, a1hi.w};
            float av2[8] = {a2lo.x, a2lo.y, a2lo.z, a2lo.w, a2hi.x, a2hi.y, a2hi.z, a2hi.w};
#pragma unroll
            for (int i = 0; i < 8; i++) {
                unsigned long long p1, p2;
                PACK2(p1, av1[i]);
                PACK2(p2, av2[i]);
                FMA2(c1[i][0], p1, b0); FMA2(c1[i][1], p1, b1);
                FMA2(c1[i][2], p1, b2); FMA2(c1[i][3], p1, b3);
                FMA2(c2[i][0], p2, b0); FMA2(c2[i][1], p2, b1);
                FMA2(c2[i][2], p2, b2); FMA2(c2[i][3], p2, b3);
            }
        }
        __syncthreads();
    }

    bool tail = (bn + GBN > N_ENTC);
    float* orow_base = out + off;
#pragma unroll
    for (int i = 0; i < 8; i++) {
        int gm = bm + m0 + i;
        float es[8], dd[8];
#pragma unroll
        for (int j = 0; j < 4; j++) {
            es[2 * j]     = __uint_as_float((unsigned)c1[i][j]);
            es[2 * j + 1] = __uint_as_float((unsigned)(c1[i][j] >> 32));
            dd[2 * j]     = __uint_as_float((unsigned)c2[i][j]);
            dd[2 * j + 1] = __uint_as_float((unsigned)(c2[i][j] >> 32));
        }
        float mx = -3.0e38f, sq = 0.f;
        float* orow = orow_base + (size_t)gm * N_ENTC + bn + n0;
        if (!tail) {
            float4 e4a = *reinterpret_cast<const float4*>(&enb[bn + n0]);
            float4 e4b = *reinterpret_cast<const float4*>(&enb[bn + n0 + 4]);
            float4 i4a = *reinterpret_cast<const float4*>(&infb[bn + n0]);
            float4 i4b = *reinterpret_cast<const float4*>(&infb[bn + n0 + 4]);
            float4 v4a = *reinterpret_cast<const float4*>(&dbvec[(size_t)gm * N_ENTC + bn + n0]);
            float4 v4b = *reinterpret_cast<const float4*>(&dbvec[(size_t)gm * N_ENTC + bn + n0 + 4]);
            float eb[8] = {e4a.x, e4a.y, e4a.z, e4a.w, e4b.x, e4b.y, e4b.z, e4b.w};
            float ib[8] = {i4a.x, i4a.y, i4a.z, i4a.w, i4b.x, i4b.y, i4b.z, i4b.w};
            float vv[8] = {v4a.x, v4a.y, v4a.z, v4a.w, v4b.x, v4b.y, v4b.z, v4b.w};
#pragma unroll
            for (int j = 0; j < 8; j++) {
                es[j] += eb[j];
                mx = fmaxf(mx, es[j]);
                float df = dd[j] + ib[j] - vv[j];
                sq += df * df;
                orow[j] = es[j];
            }
        } else {
#pragma unroll
            for (int j = 0; j < 8; j++) {
                int gn = bn + n0 + j;
                if (gn < N_ENTC) {
                    es[j] += enb[gn];
                    mx = fmaxf(mx, es[j]);
                    float df = dd[j] + infb[gn] - dbvec[(size_t)gm * N_ENTC + gn];
                    sq += df * df;
                    orow[j] = es[j];
                } else {
                    es[j] = -3.0e38f;
                }
            }
        }
#pragma unroll
        for (int o = 8; o; o >>= 1) mx = fmaxf(mx, __shfl_xor_sync(0xffffffffu, mx, o));
        float z = 0.f;
#pragma unroll
        for (int j = 0; j < 8; j++) z += __expf(es[j] - mx);
#pragma unroll
        for (int o = 8; o; o >>= 1) {
            z  += __shfl_xor_sync(0xffffffffu, z, o);
            sq += __shfl_xor_sync(0xffffffffu, sq, o);
        }
        if (tx == 0) {
            g_pm[gm * PML + blockIdx.x] = mx;
            g_pz[gm * PML + blockIdx.x] = z;
            atomicAdd(&g_info_partial[gm], sq);
        }
    }
}

// ---------------- softmax partial reduce ---------------------------------------
__global__ __launch_bounds__(256) void k_stats_reduce() {
    int b = blockIdx.x, t = threadIdx.x;
    __shared__ float sm[256], sz[256];
    float m = (t < NBLKN) ? g_pm[b * PML + t] : -3.0e38f;
    sm[t] = m;
    __syncthreads();
    for (int o = 128; o; o >>= 1) {
        if (t < o) sm[t] = fmaxf(sm[t], sm[t + o]);
        __syncthreads();
    }
    float M = sm[0];
    float z = (t < NBLKN) ? g_pz[b * PML + t] * __expf(m - M) : 0.f;
    sz[t] = z;
    __syncthreads();
    for (int o = 128; o; o >>= 1) {
        if (t < o) sz[t] += sz[t + o];
        __syncthreads();
    }
    if (t == 0) { g_bmax[b] = M; g_bZ[b] = sz[0]; }
}

// ---------------- final loss ----------------------------------------------------
__global__ __launch_bounds__(256) void k_final(
    const int* __restrict__ labels, const float* __restrict__ rec,
    float* __restrict__ out, int off)
{
    int b = threadIdx.x;
    int lab = labels[b];
    if (lab < 0) lab = 0;
    if (lab >= N_ENTC) lab = N_ENTC - 1;
    float es = out[off + (size_t)b * N_ENTC + lab];
    float ce = (g_bmax[b] + logf(g_bZ[b])) - es;
    float rv = ce * rec[b];
    float iv = g_info_partial[b] * g_mask[b];
    __shared__ float s1[256], s2[256];
    s1[b] = rv; s2[b] = iv;
    __syncthreads();
    for (int o = 128; o; o >>= 1) {
        if (b < o) { s1[b] += s1[b + o]; s2[b] += s2[b + o]; }
        __syncthreads();
    }
    if (b == 0) {
        float rl = s1[0];
        float loss = rl + 0.025f * (s2[0] / (float)BBC);
        if (off) {
            out[0] = loss;
            out[1 + (size_t)BBC * N_ENTC] = rl;
        }
    }
}

// ---------------- launch ---------------------------------------------------------
extern "C" void kernel_launch(void* const* d_in, const int* in_sizes, int n_in,
                              void* d_out, int out_size) {
    const int*   concept_mask = (const int*)d_in[0];
    const int*   seed_pad     = (const int*)d_in[1];
    const int*   seed_lens    = (const int*)d_in[2];
    const int*   db_ei        = (const int*)d_in[3];
    const int*   db_et        = (const int*)d_in[4];
    const int*   con_ei       = (const int*)d_in[5];
    const float* db_vec       = (const float*)d_in[6];
    const int*   labels       = (const int*)d_in[7];
    const float* rec          = (const float*)d_in[8];
    const float* concept_emb  = (const float*)d_in[9];
    const float* basis        = (const float*)d_in[10];
    const float* comp         = (const float*)d_in[11];
    const float* rgcn_root    = (const float*)d_in[12];
    const float* rgcn_bias    = (const float*)d_in[13];
    const float* gcn_w        = (const float*)d_in[14];
    const float* gcn_b        = (const float*)d_in[15];
    const float* attn_a       = (const float*)d_in[16];
    const float* attn_b       = (const float*)d_in[17];
    const float* attn_a_db    = (const float*)d_in[18];
    const float* attn_b_db    = (const float*)d_in[19];
    const float* user_norm_w  = (const float*)d_in[20];
    const float* user_norm_b  = (const float*)d_in[21];
    const float* gate_norm_w  = (const float*)d_in[22];
    const float* gate_norm_b  = (const float*)d_in[23];
    const float* info_con_w   = (const float*)d_in[24];
    const float* info_con_b   = (const float*)d_in[25];
    const float* info_out_db_b= (const float*)d_in[26];
    const float* output_en_b  = (const float*)d_in[27];
    float* out = (float*)d_out;

    long long total = (long long)BBC * N_ENTC;
    int off = ((long long)out_size >= total + 2) ? 1 : 0;

    static cudaStream_t s1 = nullptr, s2 = nullptr;
    static cudaEvent_t eF = nullptr, eZ = nullptr, eJ1 = nullptr, eJ2 = nullptr;
    if (s1 == nullptr) {
        cudaStreamCreateWithFlags(&s1, cudaStreamNonBlocking);
        cudaStreamCreateWithFlags(&s2, cudaStreamNonBlocking);
        cudaEventCreateWithFlags(&eF, cudaEventDisableTiming);
        cudaEventCreateWithFlags(&eZ, cudaEventDisableTiming);
        cudaEventCreateWithFlags(&eJ1, cudaEventDisableTiming);
        cudaEventCreateWithFlags(&eJ2, cudaEventDisableTiming);
    }

    cudaEventRecord(eF, 0);
    cudaStreamWaitEvent(s1, eF, 0);
    k_wbuild<<<(N_ENTC * 32 + 255) / 256, 256, 0, s1>>>(comp, basis);

    k_zero<<<3750, 256>>>();
    cudaEventRecord(eZ, 0);
    cudaStreamWaitEvent(s1, eZ, 0);
    cudaStreamWaitEvent(s2, eZ, 0);

    // chain 1: RGCN/db path
    k_rgcn_scatter<<<(E_DBC * 32 + 255) / 256, 256, 0, s1>>>(db_ei, db_et);
    k_rgcn_fin<<<(N_ENTC * DIMC / 4 + 255) / 256, 256, 0, s1>>>(rgcn_root, rgcn_bias);
    k_attn_e<true><<<BBC * SSC / EM, 256, 0, s1>>>(seed_pad, attn_a_db, attn_b_db);
    k_attn_fin_db<<<BBC, 128, 0, s1>>>(seed_pad, seed_lens);

    // chain 2: GCN/concept path
    k_deg<<<(E_CONC + 255) / 256, 256, 0, s2>>>(con_ei);
    k_dinv<<<(N_CONC + 255) / 256, 256, 0, s2>>>();
    k_xw<<<(N_CONC + XR2 - 1) / XR2, 128, 0, s2>>>(concept_emb, gcn_w);
    k_gcn_scatter<<<(E_CONC * 32 + 255) / 256, 256, 0, s2>>>(con_ei);
    k_gcn_fin<<<(N_CONC * DIMC / 4 + 255) / 256, 256, 0, s2>>>(gcn_b);
    k_attn_e<false><<<BBC * LCC / EM, 256, 0, s2>>>(concept_mask, attn_a, attn_b);
    k_attn_fin_con<<<BBC, 128, 0, s2>>>(concept_mask);

    cudaEventRecord(eJ1, s1);
    cudaEventRecord(eJ2, s2);
    cudaStreamWaitEvent(0, eJ1, 0);
    cudaStreamWaitEvent(0, eJ2, 0);

    k_fuse<<<BBC, 128>>>(user_norm_w, user_norm_b, gate_norm_w, gate_norm_b,
                         info_con_w, info_con_b);
    dim3 gg(NBLKN, BBC / GBM);
    k_score_gemm<<<gg, 128>>>(output_en_b, info_out_db_b, db_vec, out, off);
    k_stats_reduce<<<BBC, 256>>>();
    k_final<<<1, 256>>>(labels, rec, out, off);
}